// round 5
// baseline (speedup 1.0000x reference)
#include <cuda_runtime.h>

#define PITCH 129                                   // float2 pitch, conflict-free columns
#define NF_MAX 2850                                 // >= 2821 masked frequencies
#define SMEM_BYTES (128 * PITCH * sizeof(float2))   // 132096 B

// ---------------- device scratch ------------------------------------------------
__device__ float2 g_E[128];                         // exp(-2*pi*i*k/128)
__device__ int    g_maskUV[NF_MAX];
__device__ int    g_conjRank[NF_MAX];
__device__ int    g_offA[NF_MAX];                   // brev7(u)*PITCH + brev7(v)
__device__ int    g_offB[NF_MAX];                   // conj bin
__device__ float2 g_A[61 * 3 * 4096];               // [c][p][o*64+i] weight v-partials
__device__ float4 g_Xf4[(size_t)NF_MAX * 512];      // [f][i*16+b] /2
__device__ float4 g_Yf4[(size_t)NF_MAX * 512];      // [f][b*64+o] /2
#define g_Xf ((float2*)g_Xf4)
#define g_Yf ((float2*)g_Yf4)

__device__ __forceinline__ int brev7(int x) { return (int)(__brev((unsigned)x) >> 25); }
__device__ __forceinline__ float2 cadd(float2 a, float2 b){ return make_float2(a.x+b.x, a.y+b.y); }
__device__ __forceinline__ float2 csub(float2 a, float2 b){ return make_float2(a.x-b.x, a.y-b.y); }
__device__ __forceinline__ float2 cmul(float2 a, float2 b){ return make_float2(a.x*b.x - a.y*b.y, a.x*b.y + a.y*b.x); }
__device__ __forceinline__ float2 cjmul(float2 b, float2 w){
    return make_float2(b.x*w.x + b.y*w.y, b.y*w.x - b.x*w.y); }
__device__ __forceinline__ float2 mulnegi(float2 a){ return make_float2(a.y, -a.x); }
__device__ __forceinline__ float2 mulposi(float2 a){ return make_float2(-a.y, a.x); }

// ---------------- init ----------------------------------------------------------
__device__ __forceinline__ int vmaxOf(int rem){
    int vm = __float2int_rd(sqrtf((float)rem));
    while (vm*vm > rem) vm--;
    while ((vm+1)*(vm+1) <= rem) vm++;
    return vm;
}
__device__ int rankOf(int u, int v){
    int rank = 0;
    for (int up = 0; up < u; up++){
        int dup = (up < 64) ? up : up - 128;
        int rem = 900 - dup*dup;
        if (rem >= 0) rank += 2*vmaxOf(rem) + 1;
    }
    int du = (u < 64) ? u : u - 128;
    int vm = vmaxOf(900 - du*du);
    return rank + ((v <= vm) ? v : v - (128 - vm) + vm + 1);
}

__global__ void init_tables(){
    int t = blockIdx.x * blockDim.x + threadIdx.x;
    if (t <= 32){
        double ang = -6.283185307179586476925286766559 * (double)t / 128.0;
        float c = (float)cos(ang), s = (float)sin(ang);
        if (t == 0)      { g_E[0]  = make_float2(1.f, 0.f);  g_E[64] = make_float2(-1.f, 0.f); }
        else if (t == 32){ g_E[32] = make_float2(0.f, -1.f); g_E[96] = make_float2(0.f, 1.f); }
        else {
            g_E[t]       = make_float2( c,  s);
            g_E[64 - t]  = make_float2(-c,  s);
            g_E[64 + t]  = make_float2(-c, -s);
            g_E[128 - t] = make_float2( c, -s);
        }
    }
    if (t < 16384){
        int u = t >> 7, v = t & 127;
        int du = (u < 64) ? u : u - 128;
        int dv = (v < 64) ? v : v - 128;
        if (du*du + dv*dv <= 900){
            int r = rankOf(u, v);
            int uc = (128 - u) & 127, vc = (128 - v) & 127;
            g_maskUV[r]   = t;
            g_conjRank[r] = rankOf(uc, vc);
            g_offA[r]     = brev7(u)  * PITCH + brev7(v);
            g_offB[r]     = brev7(uc) * PITCH + brev7(vc);
        }
    }
}

// ---------------- weight v-partials: A_p(v)[oi] = sum_q w[oi,p,q] E[vq] --------
__global__ void prep_A(const float* __restrict__ wgt){
    int c = blockIdx.x;                      // 0..60
    int v = (c <= 30) ? c : c + 67;
    float2 e1 = g_E[v], e2 = g_E[(2*v) & 127];
    for (int oi = threadIdx.x; oi < 4096; oi += 256){
        const float* w9 = wgt + oi*9;
        #pragma unroll
        for (int p = 0; p < 3; p++){
            float w0 = w9[p*3], w1 = w9[p*3+1], w2 = w9[p*3+2];
            float2 acc;
            acc.x = w0 + w1*e1.x + w2*e2.x;
            acc.y =      w1*e1.y + w2*e2.y;
            g_A[((size_t)c*3 + p)*4096 + oi] = acc;
        }
    }
}

// ---------------- radix bodies (verified R2 math, per work item) ---------------
// forward DIF radix-8: stages dist 64,32,16; base = line + j*es, stp = 16*es
__device__ __forceinline__ void dif8_body(float2* d, const float2* tw, int base, int stp, int j){
    float2 x[8];
    #pragma unroll
    for (int m = 0; m < 8; m++) x[m] = d[base + m*stp];
    #pragma unroll
    for (int m = 0; m < 4; m++){
        float2 a = x[m], b = x[m+4];
        x[m] = cadd(a,b); x[m+4] = cmul(csub(a,b), tw[j + 16*m]);
    }
    {
        float2 w0 = tw[2*j], w1 = tw[2*j + 32], a, b;
        a=x[0]; b=x[2]; x[0]=cadd(a,b); x[2]=cmul(csub(a,b), w0);
        a=x[1]; b=x[3]; x[1]=cadd(a,b); x[3]=cmul(csub(a,b), w1);
        a=x[4]; b=x[6]; x[4]=cadd(a,b); x[6]=cmul(csub(a,b), w0);
        a=x[5]; b=x[7]; x[5]=cadd(a,b); x[7]=cmul(csub(a,b), w1);
    }
    {
        float2 w = tw[4*j];
        #pragma unroll
        for (int m = 0; m < 8; m += 2){
            float2 a = x[m], b = x[m+1];
            x[m] = cadd(a,b); x[m+1] = cmul(csub(a,b), w);
        }
    }
    #pragma unroll
    for (int m = 0; m < 8; m++) d[base + m*stp] = x[m];
}

// forward DIF radix-16: stages dist 8,4,2,1; base = line + blk*16*es
__device__ __forceinline__ void dif16_body(float2* d, const float2* tw, int base, int es){
    float2 x[16];
    #pragma unroll
    for (int m = 0; m < 16; m++) x[m] = d[base + m*es];
    #pragma unroll
    for (int m = 0; m < 8; m++){
        float2 a = x[m], b = x[m+8];
        x[m] = cadd(a,b); x[m+8] = cmul(csub(a,b), tw[8*m]);
    }
    #pragma unroll
    for (int m = 0; m < 4; m++){
        float2 w = tw[16*m], a, b;
        a=x[m];   b=x[m+4];  x[m]  =cadd(a,b); x[m+4] =cmul(csub(a,b), w);
        a=x[m+8]; b=x[m+12]; x[m+8]=cadd(a,b); x[m+12]=cmul(csub(a,b), w);
    }
    #pragma unroll
    for (int g = 0; g < 4; g++){
        int b0 = 4*g; float2 a, b;
        a=x[b0];   b=x[b0+2]; x[b0]  =cadd(a,b); x[b0+2]=csub(a,b);
        a=x[b0+1]; b=x[b0+3]; x[b0+1]=cadd(a,b); x[b0+3]=mulnegi(csub(a,b));
    }
    #pragma unroll
    for (int m = 0; m < 16; m += 2){
        float2 a = x[m], b = x[m+1];
        x[m] = cadd(a,b); x[m+1] = csub(a,b);
    }
    #pragma unroll
    for (int m = 0; m < 16; m++) d[base + m*es] = x[m];
}

// inverse DIT radix-16: stages dist 1,2,4,8
__device__ __forceinline__ void dit16_body(float2* d, const float2* tw, int base, int es){
    float2 x[16];
    #pragma unroll
    for (int m = 0; m < 16; m++) x[m] = d[base + m*es];
    #pragma unroll
    for (int m = 0; m < 16; m += 2){
        float2 a = x[m], b = x[m+1];
        x[m] = cadd(a,b); x[m+1] = csub(a,b);
    }
    #pragma unroll
    for (int g = 0; g < 4; g++){
        int b0 = 4*g; float2 a, tt;
        a=x[b0];   tt=x[b0+2];          x[b0]  =cadd(a,tt); x[b0+2]=csub(a,tt);
        a=x[b0+1]; tt=mulposi(x[b0+3]); x[b0+1]=cadd(a,tt); x[b0+3]=csub(a,tt);
    }
    #pragma unroll
    for (int m = 0; m < 4; m++){
        float2 w = tw[16*m], a, tt;
        a=x[m];   tt=cjmul(x[m+4],  w); x[m]  =cadd(a,tt); x[m+4] =csub(a,tt);
        a=x[m+8]; tt=cjmul(x[m+12], w); x[m+8]=cadd(a,tt); x[m+12]=csub(a,tt);
    }
    #pragma unroll
    for (int m = 0; m < 8; m++){
        float2 a = x[m], tt = cjmul(x[m+8], tw[8*m]);
        x[m] = cadd(a,tt); x[m+8] = csub(a,tt);
    }
    #pragma unroll
    for (int m = 0; m < 16; m++) d[base + m*es] = x[m];
}

// inverse DIT radix-8: stages dist 16,32,64
__device__ __forceinline__ void dit8_body(float2* d, const float2* tw, int base, int stp, int j){
    float2 x[8];
    #pragma unroll
    for (int m = 0; m < 8; m++) x[m] = d[base + m*stp];
    {
        float2 w = tw[4*j];
        #pragma unroll
        for (int m = 0; m < 8; m += 2){
            float2 a = x[m], tt = cjmul(x[m+1], w);
            x[m] = cadd(a,tt); x[m+1] = csub(a,tt);
        }
    }
    {
        float2 w0 = tw[2*j], w1 = tw[2*j + 32], a, tt;
        a=x[0]; tt=cjmul(x[2], w0); x[0]=cadd(a,tt); x[2]=csub(a,tt);
        a=x[1]; tt=cjmul(x[3], w1); x[1]=cadd(a,tt); x[3]=csub(a,tt);
        a=x[4]; tt=cjmul(x[6], w0); x[4]=cadd(a,tt); x[6]=csub(a,tt);
        a=x[5]; tt=cjmul(x[7], w1); x[5]=cadd(a,tt); x[7]=csub(a,tt);
    }
    #pragma unroll
    for (int m = 0; m < 4; m++){
        float2 a = x[m], tt = cjmul(x[m+4], tw[j + 16*m]);
        x[m] = cadd(a,tt); x[m+4] = csub(a,tt);
    }
    #pragma unroll
    for (int m = 0; m < 8; m++) d[base + m*stp] = x[m];
}

// fill s_vpos: bit-rev column positions of the 61 masked v + 3 unused pad columns
__device__ __forceinline__ void fill_vpos(int* s_vpos, int tid){
    if (tid < 61){
        int v = (tid < 31) ? tid : tid + 67;
        s_vpos[tid] = brev7(v);
    } else if (tid < 64){
        s_vpos[tid] = 124 + (tid - 61);   // columns 124,125,126: brev7 -> v=31,95,63 (unmasked)
    }
}

// ---------------- forward: pack 2 real channels per complex FFT ----------------
__global__ __launch_bounds__(1024, 1) void fwd_kernel(const float* __restrict__ x, int nMask){
    extern __shared__ float2 data[];
    __shared__ float2 tw[64];
    __shared__ int s_vpos[64];
    int tid = threadIdx.x;
    if (tid < 64) tw[tid] = g_E[tid];
    fill_vpos(s_vpos, tid);
    int b = blockIdx.x >> 5, ip = blockIdx.x & 31;
    int i0 = 2*ip;
    const float* s0 = x + (size_t)(b*64 + i0) * 16384;
    const float* s1 = s0 + 16384;
    for (int idx = tid; idx < 16384; idx += 1024)
        data[(idx >> 7)*PITCH + (idx & 127)] = make_float2(s0[idx], s1[idx]);
    __syncthreads();

    // rows: DIF radix-8 then radix-16 (along v, stride 1)
    #pragma unroll
    for (int it = 0; it < 2; it++){
        int t = tid + it*1024;
        dif8_body(data, tw, (t & 127)*PITCH + (t >> 7), 16, t >> 7);
    }
    __syncthreads();
    dif16_body(data, tw, (tid & 127)*PITCH + (tid >> 7)*16, 1);
    __syncthreads();

    // cols: DIF on 64 pruned columns (along h, stride PITCH)
    {
        int j = tid & 15, l = tid >> 4;     // 64 lines x 16
        dif8_body(data, tw, s_vpos[l] + j*PITCH, 16*PITCH, j);
    }
    __syncthreads();
    if (tid < 512){
        int l = tid & 63, blk = tid >> 6;
        dif16_body(data, tw, s_vpos[l] + blk*16*PITCH, PITCH);
    }
    __syncthreads();

    // gather + Hermitian split; g_Xf layout [f][i*16+b]
    for (int f = tid; f < nMask; f += 1024){
        int pr = g_conjRank[f];
        if (pr < f) continue;
        float2 z  = data[g_offA[f]];
        float2 zc = data[g_offB[f]];
        float2 X0 = make_float2(0.5f*(z.x + zc.x), 0.5f*(z.y - zc.y));
        float2 X1 = make_float2(0.5f*(z.y + zc.y), 0.5f*(zc.x - z.x));
        size_t base = (size_t)f*1024 + i0*16 + b;
        g_Xf[base]      = X0;
        g_Xf[base + 16] = X1;
    }
}

// ---------------- per-frequency channel mix (primary bins only) ----------------
__global__ __launch_bounds__(256) void mix_kernel(int nMask){
    __shared__ float4 Xs4[512];      // [i][b]
    __shared__ float2 Ws[64 * 65];   // [o][i]
    int f = blockIdx.x;
    int pr = g_conjRank[f];
    if (pr < f) return;
    int tid = threadIdx.x;
    int uv = g_maskUV[f];
    int u = uv >> 7, v = uv & 127;
    int c = (v <= 30) ? v : v - 67;
    float2 eu1 = g_E[u], eu2 = g_E[(2*u) & 127];
    for (int j = tid; j < 512; j += 256) Xs4[j] = g_Xf4[(size_t)f*512 + j];
    const float2* Ac = g_A + (size_t)c*3*4096;
    for (int oi = tid; oi < 4096; oi += 256){
        float2 a0 = Ac[oi], a1 = Ac[oi + 4096], a2 = Ac[oi + 8192];
        float2 wv;
        wv.x = a0.x + a1.x*eu1.x - a1.y*eu1.y + a2.x*eu2.x - a2.y*eu2.y;
        wv.y = a0.y + a1.x*eu1.y + a1.y*eu1.x + a2.x*eu2.y + a2.y*eu2.x;
        Ws[(oi >> 6)*65 + (oi & 63)] = wv;
    }
    __syncthreads();
    int o  = tid & 63;
    int bb = (tid >> 6) << 2;
    float2 a0 = make_float2(0.f,0.f), a1 = a0, a2 = a0, a3 = a0;
    const float2* wrow = &Ws[o * 65];
    int xbase = bb >> 1;
    #pragma unroll 8
    for (int i = 0; i < 64; i++){
        float2 w  = wrow[i];
        float4 xa = Xs4[i*8 + xbase];
        float4 xb = Xs4[i*8 + xbase + 1];
        a0.x += xa.x*w.x - xa.y*w.y;  a0.y += xa.x*w.y + xa.y*w.x;
        a1.x += xa.z*w.x - xa.w*w.y;  a1.y += xa.z*w.y + xa.w*w.x;
        a2.x += xb.x*w.x - xb.y*w.y;  a2.y += xb.x*w.y + xb.y*w.x;
        a3.x += xb.z*w.x - xb.w*w.y;  a3.y += xb.z*w.y + xb.w*w.x;
    }
    size_t bf = (size_t)f*1024, bp = (size_t)pr*1024;
    g_Yf[bf + (bb+0)*64 + o] = a0;
    g_Yf[bf + (bb+1)*64 + o] = a1;
    g_Yf[bf + (bb+2)*64 + o] = a2;
    g_Yf[bf + (bb+3)*64 + o] = a3;
    if (pr != f){
        g_Yf[bp + (bb+0)*64 + o] = make_float2(a0.x, -a0.y);
        g_Yf[bp + (bb+1)*64 + o] = make_float2(a1.x, -a1.y);
        g_Yf[bp + (bb+2)*64 + o] = make_float2(a2.x, -a2.y);
        g_Yf[bp + (bb+3)*64 + o] = make_float2(a3.x, -a3.y);
    }
}

// ---------------- inverse: pack 2 real outputs per complex IFFT ----------------
__global__ __launch_bounds__(1024, 1) void inv_kernel(float* __restrict__ out,
                                                      const float* __restrict__ bias, int nMask){
    extern __shared__ float2 data[];
    __shared__ float2 tw[64];
    __shared__ int s_vpos[64];
    int tid = threadIdx.x;
    if (tid < 64) tw[tid] = g_E[tid];
    fill_vpos(s_vpos, tid);
    int b = blockIdx.x >> 5, op = blockIdx.x & 31;
    int o0 = 2*op;
    int bsrc = (b + 8) & 15;
    int osrc = (o0 + 32) & 63;
    for (int idx = tid; idx < 128*PITCH; idx += 1024) data[idx] = make_float2(0.f, 0.f);
    __syncthreads();

    // scatter masked bins at (brev u, brev v); Z = Y0 + i*Y1
    for (int f = tid; f < nMask; f += 1024){
        float4 y = *(const float4*)&g_Yf4[(size_t)f*512 + (bsrc*64 + osrc)/2];
        data[g_offA[f]] = make_float2(y.x - y.w, y.y + y.z);
    }
    __syncthreads();

    // cols: DIT on 64 pruned columns (u-transform, stride PITCH)
    if (tid < 512){
        int l = tid & 63, blk = tid >> 6;
        dit16_body(data, tw, s_vpos[l] + blk*16*PITCH, PITCH);
    }
    __syncthreads();
    {
        int j = tid & 15, l = tid >> 4;
        dit8_body(data, tw, s_vpos[l] + j*PITCH, 16*PITCH, j);
    }
    __syncthreads();

    // rows: DIT (v-transform, stride 1)
    dit16_body(data, tw, (tid & 127)*PITCH + (tid >> 7)*16, 1);
    __syncthreads();
    #pragma unroll
    for (int it = 0; it < 2; it++){
        int t = tid + it*1024;
        dit8_body(data, tw, (t & 127)*PITCH + (t >> 7), 16, t >> 7);
    }
    __syncthreads();

    float bv0 = bias[o0], bv1 = bias[o0 + 1];
    float* d0 = out + (size_t)(b*64 + o0) * 16384;
    float* d1 = d0 + 16384;
    const float sc = 1.f / 16384.f;
    for (int idx = tid; idx < 16384; idx += 1024){
        float2 v2 = data[(idx >> 7)*PITCH + (idx & 127)];
        d0[idx] = v2.x * sc + bv0;
        d1[idx] = v2.y * sc + bv1;
    }
}

// ---------------- launch --------------------------------------------------------
extern "C" void kernel_launch(void* const* d_in, const int* in_sizes, int n_in,
                              void* d_out, int out_size){
    const float* x    = (const float*)d_in[0];
    const float* wgt  = (const float*)d_in[1];
    const float* bias = (const float*)d_in[2];
    float* out = (float*)d_out;

    int nMask = 0;
    for (int u = 0; u < 128; u++){
        int du = (u < 64) ? u : u - 128;
        for (int v = 0; v < 128; v++){
            int dv = (v < 64) ? v : v - 128;
            if (du*du + dv*dv <= 900) nMask++;
        }
    }

    cudaFuncSetAttribute(fwd_kernel, cudaFuncAttributeMaxDynamicSharedMemorySize, (int)SMEM_BYTES);
    cudaFuncSetAttribute(inv_kernel, cudaFuncAttributeMaxDynamicSharedMemorySize, (int)SMEM_BYTES);

    init_tables<<<64, 256>>>();
    prep_A<<<61, 256>>>(wgt);
    fwd_kernel<<<512, 1024, SMEM_BYTES>>>(x, nMask);
    mix_kernel<<<nMask, 256>>>(nMask);
    inv_kernel<<<512, 1024, SMEM_BYTES>>>(out, bias, nMask);
}

// round 6
// speedup vs baseline: 1.0903x; 1.0903x over previous
#include <cuda_runtime.h>

#define PITCH 129                                   // float2 pitch, conflict-free columns
#define NF_MAX 2850                                 // >= 2821 masked frequencies
#define SMEM_BYTES (128 * PITCH * sizeof(float2))   // 132096 B

// ---------------- device scratch ------------------------------------------------
__device__ float2 g_E[128];                         // exp(-2*pi*i*k/128)
__device__ int    g_maskUV[NF_MAX];
__device__ int    g_conjRank[NF_MAX];
__device__ int    g_offA[NF_MAX];                   // brev7(u)*PITCH + brev7(v)
__device__ int    g_offB[NF_MAX];                   // conj bin
__device__ float2 g_A[61 * 3 * 4096];               // [c][p][o*64+i] weight v-partials
__device__ float4 g_Xf4[(size_t)NF_MAX * 512];      // [f][i*16+b] /2
__device__ float4 g_Yf4[(size_t)NF_MAX * 512];      // [f][b*64+o] /2
#define g_Xf ((float2*)g_Xf4)
#define g_Yf ((float2*)g_Yf4)

__device__ __forceinline__ int brev7(int x) { return (int)(__brev((unsigned)x) >> 25); }
__device__ __forceinline__ float2 cadd(float2 a, float2 b){ return make_float2(a.x+b.x, a.y+b.y); }
__device__ __forceinline__ float2 csub(float2 a, float2 b){ return make_float2(a.x-b.x, a.y-b.y); }
__device__ __forceinline__ float2 cmul(float2 a, float2 b){ return make_float2(a.x*b.x - a.y*b.y, a.x*b.y + a.y*b.x); }
__device__ __forceinline__ float2 cjmul(float2 b, float2 w){
    return make_float2(b.x*w.x + b.y*w.y, b.y*w.x - b.x*w.y); }
__device__ __forceinline__ float2 mulnegi(float2 a){ return make_float2(a.y, -a.x); }
__device__ __forceinline__ float2 mulposi(float2 a){ return make_float2(-a.y, a.x); }

// ---------------- init (O(1) per thread via shared prefix sum) ------------------
__device__ __forceinline__ int vmaxOf(int rem){
    int vm = __float2int_rd(sqrtf((float)rem));
    while (vm*vm > rem) vm--;
    while ((vm+1)*(vm+1) <= rem) vm++;
    return vm;
}

__global__ __launch_bounds__(1024) void init_tables(){
    __shared__ int rowBase[128];
    __shared__ int vmax[128];
    int tid = threadIdx.x;
    if (blockIdx.x == 0 && tid <= 32){
        double ang = -6.283185307179586476925286766559 * (double)tid / 128.0;
        float c = (float)cos(ang), s = (float)sin(ang);
        if (tid == 0)      { g_E[0]  = make_float2(1.f, 0.f);  g_E[64] = make_float2(-1.f, 0.f); }
        else if (tid == 32){ g_E[32] = make_float2(0.f, -1.f); g_E[96] = make_float2(0.f, 1.f); }
        else {
            g_E[tid]       = make_float2( c,  s);
            g_E[64 - tid]  = make_float2(-c,  s);
            g_E[64 + tid]  = make_float2(-c, -s);
            g_E[128 - tid] = make_float2( c, -s);
        }
    }
    if (tid < 128){
        int du = (tid < 64) ? tid : tid - 128;
        int rem = 900 - du*du;
        vmax[tid] = (rem >= 0) ? vmaxOf(rem) : -1;
    }
    __syncthreads();
    if (tid == 0){
        int s = 0;
        for (int u = 0; u < 128; u++){ rowBase[u] = s; if (vmax[u] >= 0) s += 2*vmax[u] + 1; }
    }
    __syncthreads();
    int t = blockIdx.x * blockDim.x + tid;
    if (t < 16384){
        int u = t >> 7, v = t & 127;
        int vm = vmax[u];
        if (vm >= 0){
            int dv = (v < 64) ? v : v - 128;
            if (dv >= -vm && dv <= vm){
                int r = rowBase[u] + ((v <= vm) ? v : v - (128 - vm) + vm + 1);
                int uc = (128 - u) & 127, vc = (128 - v) & 127;
                int vmc = vmax[uc];
                int rc = rowBase[uc] + ((vc <= vmc) ? vc : vc - (128 - vmc) + vmc + 1);
                g_maskUV[r]   = t;
                g_conjRank[r] = rc;
                g_offA[r]     = brev7(u)  * PITCH + brev7(v);
                g_offB[r]     = brev7(uc) * PITCH + brev7(vc);
            }
        }
    }
}

// ---------------- weight v-partials: A_p(v)[oi] = sum_q w[oi,p,q] E[vq] --------
__global__ void prep_A(const float* __restrict__ wgt){
    int c = blockIdx.x;                      // 0..60
    int v = (c <= 30) ? c : c + 67;
    float2 e1 = g_E[v], e2 = g_E[(2*v) & 127];
    for (int oi = threadIdx.x; oi < 4096; oi += 256){
        const float* w9 = wgt + oi*9;
        #pragma unroll
        for (int p = 0; p < 3; p++){
            float w0 = w9[p*3], w1 = w9[p*3+1], w2 = w9[p*3+2];
            float2 acc;
            acc.x = w0 + w1*e1.x + w2*e2.x;
            acc.y =      w1*e1.y + w2*e2.y;
            g_A[((size_t)c*3 + p)*4096 + oi] = acc;
        }
    }
}

// ---------------- radix bodies --------------------------------------------------
__device__ __forceinline__ void dif8_body(float2* d, const float2* tw, int base, int stp, int j){
    float2 x[8];
    #pragma unroll
    for (int m = 0; m < 8; m++) x[m] = d[base + m*stp];
    #pragma unroll
    for (int m = 0; m < 4; m++){
        float2 a = x[m], b = x[m+4];
        x[m] = cadd(a,b); x[m+4] = cmul(csub(a,b), tw[j + 16*m]);
    }
    {
        float2 w0 = tw[2*j], w1 = tw[2*j + 32], a, b;
        a=x[0]; b=x[2]; x[0]=cadd(a,b); x[2]=cmul(csub(a,b), w0);
        a=x[1]; b=x[3]; x[1]=cadd(a,b); x[3]=cmul(csub(a,b), w1);
        a=x[4]; b=x[6]; x[4]=cadd(a,b); x[6]=cmul(csub(a,b), w0);
        a=x[5]; b=x[7]; x[5]=cadd(a,b); x[7]=cmul(csub(a,b), w1);
    }
    {
        float2 w = tw[4*j];
        #pragma unroll
        for (int m = 0; m < 8; m += 2){
            float2 a = x[m], b = x[m+1];
            x[m] = cadd(a,b); x[m+1] = cmul(csub(a,b), w);
        }
    }
    #pragma unroll
    for (int m = 0; m < 8; m++) d[base + m*stp] = x[m];
}

__device__ __forceinline__ void dif16_body(float2* d, const float2* tw, int base, int es){
    float2 x[16];
    #pragma unroll
    for (int m = 0; m < 16; m++) x[m] = d[base + m*es];
    #pragma unroll
    for (int m = 0; m < 8; m++){
        float2 a = x[m], b = x[m+8];
        x[m] = cadd(a,b); x[m+8] = cmul(csub(a,b), tw[8*m]);
    }
    #pragma unroll
    for (int m = 0; m < 4; m++){
        float2 w = tw[16*m], a, b;
        a=x[m];   b=x[m+4];  x[m]  =cadd(a,b); x[m+4] =cmul(csub(a,b), w);
        a=x[m+8]; b=x[m+12]; x[m+8]=cadd(a,b); x[m+12]=cmul(csub(a,b), w);
    }
    #pragma unroll
    for (int g = 0; g < 4; g++){
        int b0 = 4*g; float2 a, b;
        a=x[b0];   b=x[b0+2]; x[b0]  =cadd(a,b); x[b0+2]=csub(a,b);
        a=x[b0+1]; b=x[b0+3]; x[b0+1]=cadd(a,b); x[b0+3]=mulnegi(csub(a,b));
    }
    #pragma unroll
    for (int m = 0; m < 16; m += 2){
        float2 a = x[m], b = x[m+1];
        x[m] = cadd(a,b); x[m+1] = csub(a,b);
    }
    #pragma unroll
    for (int m = 0; m < 16; m++) d[base + m*es] = x[m];
}

__device__ __forceinline__ void dit16_body(float2* d, const float2* tw, int base, int es){
    float2 x[16];
    #pragma unroll
    for (int m = 0; m < 16; m++) x[m] = d[base + m*es];
    #pragma unroll
    for (int m = 0; m < 16; m += 2){
        float2 a = x[m], b = x[m+1];
        x[m] = cadd(a,b); x[m+1] = csub(a,b);
    }
    #pragma unroll
    for (int g = 0; g < 4; g++){
        int b0 = 4*g; float2 a, tt;
        a=x[b0];   tt=x[b0+2];          x[b0]  =cadd(a,tt); x[b0+2]=csub(a,tt);
        a=x[b0+1]; tt=mulposi(x[b0+3]); x[b0+1]=cadd(a,tt); x[b0+3]=csub(a,tt);
    }
    #pragma unroll
    for (int m = 0; m < 4; m++){
        float2 w = tw[16*m], a, tt;
        a=x[m];   tt=cjmul(x[m+4],  w); x[m]  =cadd(a,tt); x[m+4] =csub(a,tt);
        a=x[m+8]; tt=cjmul(x[m+12], w); x[m+8]=cadd(a,tt); x[m+12]=csub(a,tt);
    }
    #pragma unroll
    for (int m = 0; m < 8; m++){
        float2 a = x[m], tt = cjmul(x[m+8], tw[8*m]);
        x[m] = cadd(a,tt); x[m+8] = csub(a,tt);
    }
    #pragma unroll
    for (int m = 0; m < 16; m++) d[base + m*es] = x[m];
}

__device__ __forceinline__ void dit8_body(float2* d, const float2* tw, int base, int stp, int j){
    float2 x[8];
    #pragma unroll
    for (int m = 0; m < 8; m++) x[m] = d[base + m*stp];
    {
        float2 w = tw[4*j];
        #pragma unroll
        for (int m = 0; m < 8; m += 2){
            float2 a = x[m], tt = cjmul(x[m+1], w);
            x[m] = cadd(a,tt); x[m+1] = csub(a,tt);
        }
    }
    {
        float2 w0 = tw[2*j], w1 = tw[2*j + 32], a, tt;
        a=x[0]; tt=cjmul(x[2], w0); x[0]=cadd(a,tt); x[2]=csub(a,tt);
        a=x[1]; tt=cjmul(x[3], w1); x[1]=cadd(a,tt); x[3]=csub(a,tt);
        a=x[4]; tt=cjmul(x[6], w0); x[4]=cadd(a,tt); x[6]=csub(a,tt);
        a=x[5]; tt=cjmul(x[7], w1); x[5]=cadd(a,tt); x[7]=csub(a,tt);
    }
    #pragma unroll
    for (int m = 0; m < 4; m++){
        float2 a = x[m], tt = cjmul(x[m+4], tw[j + 16*m]);
        x[m] = cadd(a,tt); x[m+4] = csub(a,tt);
    }
    #pragma unroll
    for (int m = 0; m < 8; m++) d[base + m*stp] = x[m];
}

// bit-rev column positions of the 61 masked v + 3 pad (unmasked) columns
__device__ __forceinline__ void fill_vpos(int* s_vpos, int tid){
    if (tid < 61){
        int v = (tid < 31) ? tid : tid + 67;
        s_vpos[tid] = brev7(v);
    } else if (tid < 64){
        s_vpos[tid] = 124 + (tid - 61);   // brev7 -> v = 31,95,63 (unmasked, harmless)
    }
}

// ---------------- forward: pack 2 real channels per complex FFT ----------------
__global__ __launch_bounds__(512) void fwd_kernel(const float* __restrict__ x, int nMask){
    extern __shared__ float2 data[];
    __shared__ float2 tw[64];
    __shared__ int s_vpos[64];
    int tid = threadIdx.x;
    if (tid < 64) tw[tid] = g_E[tid];
    fill_vpos(s_vpos, tid);
    int b = blockIdx.x >> 5, ip = blockIdx.x & 31;
    int i0 = 2*ip;
    const float* s0 = x + (size_t)(b*64 + i0) * 16384;
    const float* s1 = s0 + 16384;
    for (int idx = tid; idx < 16384; idx += 512)
        data[(idx >> 7)*PITCH + (idx & 127)] = make_float2(s0[idx], s1[idx]);
    __syncthreads();

    // rows (v), DIF radix-8: 2048 items
    #pragma unroll
    for (int it = 0; it < 4; it++){
        int t = tid + it*512;
        dif8_body(data, tw, (t & 127)*PITCH + (t >> 7), 16, t >> 7);
    }
    __syncthreads();
    // rows (v), DIF radix-16: 1024 items
    #pragma unroll
    for (int it = 0; it < 2; it++){
        int t = tid + it*512;
        dif16_body(data, tw, (t & 127)*PITCH + (t >> 7)*16, 1);
    }
    __syncthreads();
    // cols (u) on 64 pruned columns, DIF radix-8: 1024 items
    #pragma unroll
    for (int it = 0; it < 2; it++){
        int t = tid + it*512;
        int j = t & 15, l = t >> 4;
        dif8_body(data, tw, s_vpos[l] + j*PITCH, 16*PITCH, j);
    }
    __syncthreads();
    // cols (u), DIF radix-16: 512 items
    {
        int l = tid & 63, blk = tid >> 6;
        dif16_body(data, tw, s_vpos[l] + blk*16*PITCH, PITCH);
    }
    __syncthreads();

    // gather + Hermitian split; g_Xf layout [f][i*16+b]
    for (int f = tid; f < nMask; f += 512){
        int pr = g_conjRank[f];
        if (pr < f) continue;
        float2 z  = data[g_offA[f]];
        float2 zc = data[g_offB[f]];
        float2 X0 = make_float2(0.5f*(z.x + zc.x), 0.5f*(z.y - zc.y));
        float2 X1 = make_float2(0.5f*(z.y + zc.y), 0.5f*(zc.x - z.x));
        size_t base = (size_t)f*1024 + i0*16 + b;
        g_Xf[base]      = X0;
        g_Xf[base + 16] = X1;
    }
}

// ---------------- per-frequency channel mix (primary bins only) ----------------
__global__ __launch_bounds__(256) void mix_kernel(int nMask){
    __shared__ float4 Xs4[512];      // [i][b]
    __shared__ float2 Ws[64 * 65];   // [o][i]
    int f = blockIdx.x;
    int pr = g_conjRank[f];
    if (pr < f) return;
    int tid = threadIdx.x;
    int uv = g_maskUV[f];
    int u = uv >> 7, v = uv & 127;
    int c = (v <= 30) ? v : v - 67;
    float2 eu1 = g_E[u], eu2 = g_E[(2*u) & 127];
    for (int j = tid; j < 512; j += 256) Xs4[j] = g_Xf4[(size_t)f*512 + j];
    const float2* Ac = g_A + (size_t)c*3*4096;
    for (int oi = tid; oi < 4096; oi += 256){
        float2 a0 = Ac[oi], a1 = Ac[oi + 4096], a2 = Ac[oi + 8192];
        float2 wv;
        wv.x = a0.x + a1.x*eu1.x - a1.y*eu1.y + a2.x*eu2.x - a2.y*eu2.y;
        wv.y = a0.y + a1.x*eu1.y + a1.y*eu1.x + a2.x*eu2.y + a2.y*eu2.x;
        Ws[(oi >> 6)*65 + (oi & 63)] = wv;
    }
    __syncthreads();
    int o  = tid & 63;
    int bb = (tid >> 6) << 2;
    float2 a0 = make_float2(0.f,0.f), a1 = a0, a2 = a0, a3 = a0;
    const float2* wrow = &Ws[o * 65];
    int xbase = bb >> 1;
    #pragma unroll 8
    for (int i = 0; i < 64; i++){
        float2 w  = wrow[i];
        float4 xa = Xs4[i*8 + xbase];
        float4 xb = Xs4[i*8 + xbase + 1];
        a0.x += xa.x*w.x - xa.y*w.y;  a0.y += xa.x*w.y + xa.y*w.x;
        a1.x += xa.z*w.x - xa.w*w.y;  a1.y += xa.z*w.y + xa.w*w.x;
        a2.x += xb.x*w.x - xb.y*w.y;  a2.y += xb.x*w.y + xb.y*w.x;
        a3.x += xb.z*w.x - xb.w*w.y;  a3.y += xb.z*w.y + xb.w*w.x;
    }
    size_t bf = (size_t)f*1024, bp = (size_t)pr*1024;
    g_Yf[bf + (bb+0)*64 + o] = a0;
    g_Yf[bf + (bb+1)*64 + o] = a1;
    g_Yf[bf + (bb+2)*64 + o] = a2;
    g_Yf[bf + (bb+3)*64 + o] = a3;
    if (pr != f){
        g_Yf[bp + (bb+0)*64 + o] = make_float2(a0.x, -a0.y);
        g_Yf[bp + (bb+1)*64 + o] = make_float2(a1.x, -a1.y);
        g_Yf[bp + (bb+2)*64 + o] = make_float2(a2.x, -a2.y);
        g_Yf[bp + (bb+3)*64 + o] = make_float2(a3.x, -a3.y);
    }
}

// ---------------- inverse: pack 2 real outputs per complex IFFT ----------------
__global__ __launch_bounds__(512) void inv_kernel(float* __restrict__ out,
                                                  const float* __restrict__ bias, int nMask){
    extern __shared__ float2 data[];
    __shared__ float2 tw[64];
    __shared__ int s_vpos[64];
    int tid = threadIdx.x;
    if (tid < 64) tw[tid] = g_E[tid];
    fill_vpos(s_vpos, tid);
    int b = blockIdx.x >> 5, op = blockIdx.x & 31;
    int o0 = 2*op;
    int bsrc = (b + 8) & 15;
    int osrc = (o0 + 32) & 63;
    for (int idx = tid; idx < 128*PITCH; idx += 512) data[idx] = make_float2(0.f, 0.f);
    __syncthreads();

    // scatter masked bins at (brev u, brev v); Z = Y0 + i*Y1
    for (int f = tid; f < nMask; f += 512){
        float4 y = *(const float4*)&g_Yf4[(size_t)f*512 + (bsrc*64 + osrc)/2];
        data[g_offA[f]] = make_float2(y.x - y.w, y.y + y.z);
    }
    __syncthreads();

    // cols (u) on 64 pruned columns, DIT radix-16: 512 items
    {
        int l = tid & 63, blk = tid >> 6;
        dit16_body(data, tw, s_vpos[l] + blk*16*PITCH, PITCH);
    }
    __syncthreads();
    // cols (u), DIT radix-8: 1024 items
    #pragma unroll
    for (int it = 0; it < 2; it++){
        int t = tid + it*512;
        int j = t & 15, l = t >> 4;
        dit8_body(data, tw, s_vpos[l] + j*PITCH, 16*PITCH, j);
    }
    __syncthreads();
    // rows (v), DIT radix-16: 1024 items
    #pragma unroll
    for (int it = 0; it < 2; it++){
        int t = tid + it*512;
        dit16_body(data, tw, (t & 127)*PITCH + (t >> 7)*16, 1);
    }
    __syncthreads();
    // rows (v), DIT radix-8: 2048 items
    #pragma unroll
    for (int it = 0; it < 4; it++){
        int t = tid + it*512;
        dit8_body(data, tw, (t & 127)*PITCH + (t >> 7), 16, t >> 7);
    }
    __syncthreads();

    float bv0 = bias[o0], bv1 = bias[o0 + 1];
    float* d0 = out + (size_t)(b*64 + o0) * 16384;
    float* d1 = d0 + 16384;
    const float sc = 1.f / 16384.f;
    for (int idx = tid; idx < 16384; idx += 512){
        float2 v2 = data[(idx >> 7)*PITCH + (idx & 127)];
        d0[idx] = v2.x * sc + bv0;
        d1[idx] = v2.y * sc + bv1;
    }
}

// ---------------- launch --------------------------------------------------------
extern "C" void kernel_launch(void* const* d_in, const int* in_sizes, int n_in,
                              void* d_out, int out_size){
    const float* x    = (const float*)d_in[0];
    const float* wgt  = (const float*)d_in[1];
    const float* bias = (const float*)d_in[2];
    float* out = (float*)d_out;

    int nMask = 0;
    for (int u = 0; u < 128; u++){
        int du = (u < 64) ? u : u - 128;
        for (int v = 0; v < 128; v++){
            int dv = (v < 64) ? v : v - 128;
            if (du*du + dv*dv <= 900) nMask++;
        }
    }

    cudaFuncSetAttribute(fwd_kernel, cudaFuncAttributeMaxDynamicSharedMemorySize, (int)SMEM_BYTES);
    cudaFuncSetAttribute(inv_kernel, cudaFuncAttributeMaxDynamicSharedMemorySize, (int)SMEM_BYTES);

    init_tables<<<16, 1024>>>();
    prep_A<<<61, 256>>>(wgt);
    fwd_kernel<<<512, 512, SMEM_BYTES>>>(x, nMask);
    mix_kernel<<<nMask, 256>>>(nMask);
    inv_kernel<<<512, 512, SMEM_BYTES>>>(out, bias, nMask);
}

// round 7
// speedup vs baseline: 1.2289x; 1.1271x over previous
#include <cuda_runtime.h>

#define PITCH 129                                   // float2 pitch, conflict-free columns
#define NF_MAX 2850                                 // >= 2821 masked frequencies
#define SMEM_BYTES (128 * PITCH * sizeof(float2))   // 132096 B

// ---------------- device scratch ------------------------------------------------
__device__ float2 g_E[128];                         // exp(-2*pi*i*k/128)
__device__ int    g_maskUV[NF_MAX];
__device__ int    g_conjRank[NF_MAX];
__device__ int    g_offA[NF_MAX];                   // brev7(u)*PITCH + brev7(v)
__device__ int    g_offB[NF_MAX];                   // conj bin
__device__ float2 g_A[61 * 3 * 4096];               // [c][p][o*64+i] weight v-partials
__device__ float4 g_Xf4[(size_t)NF_MAX * 512];      // [f][i*16+b] /2
__device__ float4 g_Yf4[(size_t)NF_MAX * 512];      // [f][b*64+o] /2
#define g_Xf ((float2*)g_Xf4)
#define g_Yf ((float2*)g_Yf4)

__device__ __forceinline__ int brev7(int x) { return (int)(__brev((unsigned)x) >> 25); }
__device__ __forceinline__ float2 cadd(float2 a, float2 b){ return make_float2(a.x+b.x, a.y+b.y); }
__device__ __forceinline__ float2 csub(float2 a, float2 b){ return make_float2(a.x-b.x, a.y-b.y); }
__device__ __forceinline__ float2 cmul(float2 a, float2 b){ return make_float2(a.x*b.x - a.y*b.y, a.x*b.y + a.y*b.x); }
__device__ __forceinline__ float2 cjmul(float2 b, float2 w){
    return make_float2(b.x*w.x + b.y*w.y, b.y*w.x - b.x*w.y); }
__device__ __forceinline__ float2 mulnegi(float2 a){ return make_float2(a.y, -a.x); }
__device__ __forceinline__ float2 mulposi(float2 a){ return make_float2(-a.y, a.x); }

// ---------------- init (O(1) per thread via shared prefix sum) ------------------
__device__ __forceinline__ int vmaxOf(int rem){
    int vm = __float2int_rd(sqrtf((float)rem));
    while (vm*vm > rem) vm--;
    while ((vm+1)*(vm+1) <= rem) vm++;
    return vm;
}

__global__ __launch_bounds__(1024) void init_tables(){
    __shared__ int rowBase[128];
    __shared__ int vmax[128];
    int tid = threadIdx.x;
    if (blockIdx.x == 0 && tid <= 32){
        double ang = -6.283185307179586476925286766559 * (double)tid / 128.0;
        float c = (float)cos(ang), s = (float)sin(ang);
        if (tid == 0)      { g_E[0]  = make_float2(1.f, 0.f);  g_E[64] = make_float2(-1.f, 0.f); }
        else if (tid == 32){ g_E[32] = make_float2(0.f, -1.f); g_E[96] = make_float2(0.f, 1.f); }
        else {
            g_E[tid]       = make_float2( c,  s);
            g_E[64 - tid]  = make_float2(-c,  s);
            g_E[64 + tid]  = make_float2(-c, -s);
            g_E[128 - tid] = make_float2( c, -s);
        }
    }
    if (tid < 128){
        int du = (tid < 64) ? tid : tid - 128;
        int rem = 900 - du*du;
        vmax[tid] = (rem >= 0) ? vmaxOf(rem) : -1;
    }
    __syncthreads();
    if (tid == 0){
        int s = 0;
        for (int u = 0; u < 128; u++){ rowBase[u] = s; if (vmax[u] >= 0) s += 2*vmax[u] + 1; }
    }
    __syncthreads();
    int t = blockIdx.x * blockDim.x + tid;
    if (t < 16384){
        int u = t >> 7, v = t & 127;
        int vm = vmax[u];
        if (vm >= 0){
            int dv = (v < 64) ? v : v - 128;
            if (dv >= -vm && dv <= vm){
                int r = rowBase[u] + ((v <= vm) ? v : v - (128 - vm) + vm + 1);
                int uc = (128 - u) & 127, vc = (128 - v) & 127;
                int vmc = vmax[uc];
                int rc = rowBase[uc] + ((vc <= vmc) ? vc : vc - (128 - vmc) + vmc + 1);
                g_maskUV[r]   = t;
                g_conjRank[r] = rc;
                g_offA[r]     = brev7(u)  * PITCH + brev7(v);
                g_offB[r]     = brev7(uc) * PITCH + brev7(vc);
            }
        }
    }
}

// ---------------- weight v-partials: A_p(v)[oi] = sum_q w[oi,p,q] E[vq] --------
__global__ void prep_A(const float* __restrict__ wgt){
    int c = blockIdx.x;                      // 0..60
    int v = (c <= 30) ? c : c + 67;
    float2 e1 = g_E[v], e2 = g_E[(2*v) & 127];
    for (int oi = threadIdx.x; oi < 4096; oi += 256){
        const float* w9 = wgt + oi*9;
        #pragma unroll
        for (int p = 0; p < 3; p++){
            float w0 = w9[p*3], w1 = w9[p*3+1], w2 = w9[p*3+2];
            float2 acc;
            acc.x = w0 + w1*e1.x + w2*e2.x;
            acc.y =      w1*e1.y + w2*e2.y;
            g_A[((size_t)c*3 + p)*4096 + oi] = acc;
        }
    }
}

// ---------------- radix bodies --------------------------------------------------
__device__ __forceinline__ void dif8_body(float2* d, const float2* tw, int base, int stp, int j){
    float2 x[8];
    #pragma unroll
    for (int m = 0; m < 8; m++) x[m] = d[base + m*stp];
    #pragma unroll
    for (int m = 0; m < 4; m++){
        float2 a = x[m], b = x[m+4];
        x[m] = cadd(a,b); x[m+4] = cmul(csub(a,b), tw[j + 16*m]);
    }
    {
        float2 w0 = tw[2*j], w1 = tw[2*j + 32], a, b;
        a=x[0]; b=x[2]; x[0]=cadd(a,b); x[2]=cmul(csub(a,b), w0);
        a=x[1]; b=x[3]; x[1]=cadd(a,b); x[3]=cmul(csub(a,b), w1);
        a=x[4]; b=x[6]; x[4]=cadd(a,b); x[6]=cmul(csub(a,b), w0);
        a=x[5]; b=x[7]; x[5]=cadd(a,b); x[7]=cmul(csub(a,b), w1);
    }
    {
        float2 w = tw[4*j];
        #pragma unroll
        for (int m = 0; m < 8; m += 2){
            float2 a = x[m], b = x[m+1];
            x[m] = cadd(a,b); x[m+1] = cmul(csub(a,b), w);
        }
    }
    #pragma unroll
    for (int m = 0; m < 8; m++) d[base + m*stp] = x[m];
}

__device__ __forceinline__ void dif16_body(float2* d, const float2* tw, int base, int es){
    float2 x[16];
    #pragma unroll
    for (int m = 0; m < 16; m++) x[m] = d[base + m*es];
    #pragma unroll
    for (int m = 0; m < 8; m++){
        float2 a = x[m], b = x[m+8];
        x[m] = cadd(a,b); x[m+8] = cmul(csub(a,b), tw[8*m]);
    }
    #pragma unroll
    for (int m = 0; m < 4; m++){
        float2 w = tw[16*m], a, b;
        a=x[m];   b=x[m+4];  x[m]  =cadd(a,b); x[m+4] =cmul(csub(a,b), w);
        a=x[m+8]; b=x[m+12]; x[m+8]=cadd(a,b); x[m+12]=cmul(csub(a,b), w);
    }
    #pragma unroll
    for (int g = 0; g < 4; g++){
        int b0 = 4*g; float2 a, b;
        a=x[b0];   b=x[b0+2]; x[b0]  =cadd(a,b); x[b0+2]=csub(a,b);
        a=x[b0+1]; b=x[b0+3]; x[b0+1]=cadd(a,b); x[b0+3]=mulnegi(csub(a,b));
    }
    #pragma unroll
    for (int m = 0; m < 16; m += 2){
        float2 a = x[m], b = x[m+1];
        x[m] = cadd(a,b); x[m+1] = csub(a,b);
    }
    #pragma unroll
    for (int m = 0; m < 16; m++) d[base + m*es] = x[m];
}

__device__ __forceinline__ void dit16_body(float2* d, const float2* tw, int base, int es){
    float2 x[16];
    #pragma unroll
    for (int m = 0; m < 16; m++) x[m] = d[base + m*es];
    #pragma unroll
    for (int m = 0; m < 16; m += 2){
        float2 a = x[m], b = x[m+1];
        x[m] = cadd(a,b); x[m+1] = csub(a,b);
    }
    #pragma unroll
    for (int g = 0; g < 4; g++){
        int b0 = 4*g; float2 a, tt;
        a=x[b0];   tt=x[b0+2];          x[b0]  =cadd(a,tt); x[b0+2]=csub(a,tt);
        a=x[b0+1]; tt=mulposi(x[b0+3]); x[b0+1]=cadd(a,tt); x[b0+3]=csub(a,tt);
    }
    #pragma unroll
    for (int m = 0; m < 4; m++){
        float2 w = tw[16*m], a, tt;
        a=x[m];   tt=cjmul(x[m+4],  w); x[m]  =cadd(a,tt); x[m+4] =csub(a,tt);
        a=x[m+8]; tt=cjmul(x[m+12], w); x[m+8]=cadd(a,tt); x[m+12]=csub(a,tt);
    }
    #pragma unroll
    for (int m = 0; m < 8; m++){
        float2 a = x[m], tt = cjmul(x[m+8], tw[8*m]);
        x[m] = cadd(a,tt); x[m+8] = csub(a,tt);
    }
    #pragma unroll
    for (int m = 0; m < 16; m++) d[base + m*es] = x[m];
}

__device__ __forceinline__ void dit8_body(float2* d, const float2* tw, int base, int stp, int j){
    float2 x[8];
    #pragma unroll
    for (int m = 0; m < 8; m++) x[m] = d[base + m*stp];
    {
        float2 w = tw[4*j];
        #pragma unroll
        for (int m = 0; m < 8; m += 2){
            float2 a = x[m], tt = cjmul(x[m+1], w);
            x[m] = cadd(a,tt); x[m+1] = csub(a,tt);
        }
    }
    {
        float2 w0 = tw[2*j], w1 = tw[2*j + 32], a, tt;
        a=x[0]; tt=cjmul(x[2], w0); x[0]=cadd(a,tt); x[2]=csub(a,tt);
        a=x[1]; tt=cjmul(x[3], w1); x[1]=cadd(a,tt); x[3]=csub(a,tt);
        a=x[4]; tt=cjmul(x[6], w0); x[4]=cadd(a,tt); x[6]=csub(a,tt);
        a=x[5]; tt=cjmul(x[7], w1); x[5]=cadd(a,tt); x[7]=csub(a,tt);
    }
    #pragma unroll
    for (int m = 0; m < 4; m++){
        float2 a = x[m], tt = cjmul(x[m+4], tw[j + 16*m]);
        x[m] = cadd(a,tt); x[m+4] = csub(a,tt);
    }
    #pragma unroll
    for (int m = 0; m < 8; m++) d[base + m*stp] = x[m];
}

// bit-rev column positions of the 61 masked v + 3 pad (unmasked) columns
__device__ __forceinline__ void fill_vpos(int* s_vpos, int tid){
    if (tid < 61){
        int v = (tid < 31) ? tid : tid + 67;
        s_vpos[tid] = brev7(v);
    } else if (tid < 64){
        s_vpos[tid] = 124 + (tid - 61);   // brev7 -> v = 31,95,63 (unmasked, harmless)
    }
}

// ---------------- forward: pack 2 real channels per complex FFT ----------------
__global__ __launch_bounds__(512) void fwd_kernel(const float* __restrict__ x, int nMask){
    extern __shared__ float2 data[];
    __shared__ float2 tw[64];
    __shared__ int s_vpos[64];
    int tid = threadIdx.x;
    if (tid < 64) tw[tid] = g_E[tid];
    fill_vpos(s_vpos, tid);
    int b = blockIdx.x >> 5, ip = blockIdx.x & 31;
    int i0 = 2*ip;
    const float* s0 = x + (size_t)(b*64 + i0) * 16384;
    const float* s1 = s0 + 16384;
    for (int idx = tid; idx < 16384; idx += 512)
        data[(idx >> 7)*PITCH + (idx & 127)] = make_float2(s0[idx], s1[idx]);
    __syncthreads();

    // rows (v), DIF radix-8: 2048 items
    #pragma unroll
    for (int it = 0; it < 4; it++){
        int t = tid + it*512;
        dif8_body(data, tw, (t & 127)*PITCH + (t >> 7), 16, t >> 7);
    }
    __syncthreads();
    // rows (v), DIF radix-16: 1024 items
    #pragma unroll
    for (int it = 0; it < 2; it++){
        int t = tid + it*512;
        dif16_body(data, tw, (t & 127)*PITCH + (t >> 7)*16, 1);
    }
    __syncthreads();
    // cols (u), DIF radix-8 on 64 pruned columns: 1024 items (conflict-light mapping)
    #pragma unroll
    for (int it = 0; it < 2; it++){
        int t = tid + it*512;
        int j = t & 15, l = t >> 4;
        dif8_body(data, tw, s_vpos[l] + j*PITCH, 16*PITCH, j);
    }
    __syncthreads();
    // cols (u), DIF radix-16 on ALL 128 columns (consecutive positions -> conflict-free)
    #pragma unroll
    for (int it = 0; it < 2; it++){
        int t = tid + it*512;
        int l = t & 127, blk = t >> 7;
        dif16_body(data, tw, l + blk*16*PITCH, PITCH);
    }
    __syncthreads();

    // gather + Hermitian split; g_Xf layout [f][i*16+b]
    for (int f = tid; f < nMask; f += 512){
        int pr = g_conjRank[f];
        if (pr < f) continue;
        float2 z  = data[g_offA[f]];
        float2 zc = data[g_offB[f]];
        float2 X0 = make_float2(0.5f*(z.x + zc.x), 0.5f*(z.y - zc.y));
        float2 X1 = make_float2(0.5f*(z.y + zc.y), 0.5f*(zc.x - z.x));
        size_t base = (size_t)f*1024 + i0*16 + b;
        g_Xf[base]      = X0;
        g_Xf[base + 16] = X1;
    }
}

// ---------------- per-frequency channel mix (primary bins only) ----------------
__global__ __launch_bounds__(256) void mix_kernel(int nMask){
    __shared__ float4 Xs4[512];      // [i][b]
    __shared__ float2 Ws[64 * 65];   // [o][i]
    int f = blockIdx.x;
    int pr = g_conjRank[f];
    if (pr < f) return;
    int tid = threadIdx.x;
    int uv = g_maskUV[f];
    int u = uv >> 7, v = uv & 127;
    int c = (v <= 30) ? v : v - 67;
    float2 eu1 = g_E[u], eu2 = g_E[(2*u) & 127];
    for (int j = tid; j < 512; j += 256) Xs4[j] = g_Xf4[(size_t)f*512 + j];
    const float2* Ac = g_A + (size_t)c*3*4096;
    for (int oi = tid; oi < 4096; oi += 256){
        float2 a0 = Ac[oi], a1 = Ac[oi + 4096], a2 = Ac[oi + 8192];
        float2 wv;
        wv.x = a0.x + a1.x*eu1.x - a1.y*eu1.y + a2.x*eu2.x - a2.y*eu2.y;
        wv.y = a0.y + a1.x*eu1.y + a1.y*eu1.x + a2.x*eu2.y + a2.y*eu2.x;
        Ws[(oi >> 6)*65 + (oi & 63)] = wv;
    }
    __syncthreads();
    int o  = tid & 63;
    int bb = (tid >> 6) << 2;
    float2 a0 = make_float2(0.f,0.f), a1 = a0, a2 = a0, a3 = a0;
    const float2* wrow = &Ws[o * 65];
    int xbase = bb >> 1;
    #pragma unroll 8
    for (int i = 0; i < 64; i++){
        float2 w  = wrow[i];
        float4 xa = Xs4[i*8 + xbase];
        float4 xb = Xs4[i*8 + xbase + 1];
        a0.x += xa.x*w.x - xa.y*w.y;  a0.y += xa.x*w.y + xa.y*w.x;
        a1.x += xa.z*w.x - xa.w*w.y;  a1.y += xa.z*w.y + xa.w*w.x;
        a2.x += xb.x*w.x - xb.y*w.y;  a2.y += xb.x*w.y + xb.y*w.x;
        a3.x += xb.z*w.x - xb.w*w.y;  a3.y += xb.z*w.y + xb.w*w.x;
    }
    size_t bf = (size_t)f*1024, bp = (size_t)pr*1024;
    g_Yf[bf + (bb+0)*64 + o] = a0;
    g_Yf[bf + (bb+1)*64 + o] = a1;
    g_Yf[bf + (bb+2)*64 + o] = a2;
    g_Yf[bf + (bb+3)*64 + o] = a3;
    if (pr != f){
        g_Yf[bp + (bb+0)*64 + o] = make_float2(a0.x, -a0.y);
        g_Yf[bp + (bb+1)*64 + o] = make_float2(a1.x, -a1.y);
        g_Yf[bp + (bb+2)*64 + o] = make_float2(a2.x, -a2.y);
        g_Yf[bp + (bb+3)*64 + o] = make_float2(a3.x, -a3.y);
    }
}

// ---------------- inverse: pack 2 real outputs per complex IFFT ----------------
__global__ __launch_bounds__(512) void inv_kernel(float* __restrict__ out,
                                                  const float* __restrict__ bias, int nMask){
    extern __shared__ float2 data[];
    __shared__ float2 tw[64];
    __shared__ int s_vpos[64];
    int tid = threadIdx.x;
    if (tid < 64) tw[tid] = g_E[tid];
    fill_vpos(s_vpos, tid);
    int b = blockIdx.x >> 5, op = blockIdx.x & 31;
    int o0 = 2*op;
    int bsrc = (b + 8) & 15;
    int osrc = (o0 + 32) & 63;
    for (int idx = tid; idx < 128*PITCH; idx += 512) data[idx] = make_float2(0.f, 0.f);
    __syncthreads();

    // scatter masked bins at (brev u, brev v); Z = Y0 + i*Y1
    for (int f = tid; f < nMask; f += 512){
        float4 y = *(const float4*)&g_Yf4[(size_t)f*512 + (bsrc*64 + osrc)/2];
        data[g_offA[f]] = make_float2(y.x - y.w, y.y + y.z);
    }
    __syncthreads();

    // cols (u), DIT radix-16 on ALL 128 columns (conflict-free); zero cols stay zero
    #pragma unroll
    for (int it = 0; it < 2; it++){
        int t = tid + it*512;
        int l = t & 127, blk = t >> 7;
        dit16_body(data, tw, l + blk*16*PITCH, PITCH);
    }
    __syncthreads();
    // cols (u), DIT radix-8 on 64 pruned columns: 1024 items
    #pragma unroll
    for (int it = 0; it < 2; it++){
        int t = tid + it*512;
        int j = t & 15, l = t >> 4;
        dit8_body(data, tw, s_vpos[l] + j*PITCH, 16*PITCH, j);
    }
    __syncthreads();
    // rows (v), DIT radix-16: 1024 items
    #pragma unroll
    for (int it = 0; it < 2; it++){
        int t = tid + it*512;
        dit16_body(data, tw, (t & 127)*PITCH + (t >> 7)*16, 1);
    }
    __syncthreads();
    // rows (v), DIT radix-8: 2048 items
    #pragma unroll
    for (int it = 0; it < 4; it++){
        int t = tid + it*512;
        dit8_body(data, tw, (t & 127)*PITCH + (t >> 7), 16, t >> 7);
    }
    __syncthreads();

    float bv0 = bias[o0], bv1 = bias[o0 + 1];
    float* d0 = out + (size_t)(b*64 + o0) * 16384;
    float* d1 = d0 + 16384;
    const float sc = 1.f / 16384.f;
    for (int idx = tid; idx < 16384; idx += 512){
        float2 v2 = data[(idx >> 7)*PITCH + (idx & 127)];
        d0[idx] = v2.x * sc + bv0;
        d1[idx] = v2.y * sc + bv1;
    }
}

// ---------------- launch --------------------------------------------------------
extern "C" void kernel_launch(void* const* d_in, const int* in_sizes, int n_in,
                              void* d_out, int out_size){
    const float* x    = (const float*)d_in[0];
    const float* wgt  = (const float*)d_in[1];
    const float* bias = (const float*)d_in[2];
    float* out = (float*)d_out;

    int nMask = 0;
    for (int u = 0; u < 128; u++){
        int du = (u < 64) ? u : u - 128;
        for (int v = 0; v < 128; v++){
            int dv = (v < 64) ? v : v - 128;
            if (du*du + dv*dv <= 900) nMask++;
        }
    }

    cudaFuncSetAttribute(fwd_kernel, cudaFuncAttributeMaxDynamicSharedMemorySize, (int)SMEM_BYTES);
    cudaFuncSetAttribute(inv_kernel, cudaFuncAttributeMaxDynamicSharedMemorySize, (int)SMEM_BYTES);

    init_tables<<<16, 1024>>>();
    prep_A<<<61, 256>>>(wgt);
    fwd_kernel<<<512, 512, SMEM_BYTES>>>(x, nMask);
    mix_kernel<<<nMask, 256>>>(nMask);
    inv_kernel<<<512, 512, SMEM_BYTES>>>(out, bias, nMask);
}